// round 17
// baseline (speedup 1.0000x reference)
#include <cuda_runtime.h>
#include <cuda_bf16.h>
#include <mma.h>
#include <cstdint>

using namespace nvcuda;

// ---------------------------------------------------------------------------
// SCM_MLP: 4 chained layers  out = relu(out @ (W*mask)^T + exp(mu+sig*z)),
// activations concatenated into d_out [B, 4H].
//
// wmma/mma.sync bf16 (family-generic ISA, survives compute_103 target),
// 3-term Markidis split  A*W ~= Ahi*Whi + Ahi*Wlo + Alo*Whi, fp32 accum.
// R15: R14 (transposed weights [L][K][N], 3-stage single-barrier pipeline,
// 2 CTAs/SM) with the alignment bug fixed: LDSWT 132 -> 136 elements
// (272 B rows, 16B-aligned for cp.async/ldmatrix; 4-bank phase shift per
// row -> conflict-free 8-row LDSM phases).
// ---------------------------------------------------------------------------

static constexpr int NL = 4, NB = 4096, NH = 4096;
static constexpr int BM = 128, BN = 128, BK = 32, STAGES = 3;
static constexpr int NKT = NH / BK;             // 128 k-tiles
static constexpr int LDSA  = 40;                // A smem stride (80 B, padded)
static constexpr int LDSWT = 136;               // W-T smem stride (272 B, 16B-mult)
static constexpr int OFF_AL = 128 * LDSA;       // 5120
static constexpr int OFF_WH = 2 * 128 * LDSA;   // 10240
static constexpr int OFF_WL = OFF_WH + 32 * LDSWT;  // 14592
static constexpr int STAGE_E = OFF_WL + 32 * LDSWT; // 18944 els = 37888 B
static constexpr int SMEM_BYTES = STAGES * STAGE_E * 2;  // 113664 B
static constexpr int FB_LD = 132;               // fp32 epilogue buffer stride

// ------------------------- device scratch (.bss) ---------------------------
// g_whi/g_wlo hold TRANSPOSED masked weights: layout [L][K][N], bf16.
__device__ char g_whi[(size_t)NL * NH * NH * 2];   // 128 MiB
__device__ char g_wlo[(size_t)NL * NH * NH * 2];   // 128 MiB
__device__ char g_ahi[2][(size_t)NB * NH * 2];     // activations hi, [M][K]
__device__ char g_alo[2][(size_t)NB * NH * 2];     // activations lo, [M][K]

// ------------------------------ helpers ------------------------------------
__device__ __forceinline__ void cp16(void* s, const void* g) {
    uint32_t sa = (uint32_t)__cvta_generic_to_shared(s);
    asm volatile("cp.async.cg.shared.global [%0], [%1], 16;" :: "r"(sa), "l"(g));
}
#define CP_COMMIT() asm volatile("cp.async.commit_group;" ::: "memory")
#define CP_WAIT1()  asm volatile("cp.async.wait_group 1;" ::: "memory")

__device__ __forceinline__ uint32_t pack2(__nv_bfloat16 a, __nv_bfloat16 b) {
    __nv_bfloat162 t(a, b);
    return *reinterpret_cast<uint32_t*>(&t);
}

// ---------------------------------------------------------------------------
// Prepass: W*mask -> bf16 hi/lo, TRANSPOSED to [L][K][N] via smem 32x32 tiles.
// grid (128, 128, 4) = (n-tile, k-tile, layer), 256 threads (32x8).
// ---------------------------------------------------------------------------
__global__ void wsplitT_kernel(const float* __restrict__ w, const float* __restrict__ m) {
    __shared__ uint16_t sh[32][34], sl[32][34];
    const int l  = blockIdx.z;
    const int n0 = blockIdx.x * 32, k0 = blockIdx.y * 32;
    const int tx = threadIdx.x & 31, ty = threadIdx.x >> 5;   // 32 x 8
    const size_t base = (size_t)l * NH * NH;
#pragma unroll
    for (int i = 0; i < 4; i++) {
        int r = ty + i * 8;                      // n-row within tile
        size_t e = base + (size_t)(n0 + r) * NH + (k0 + tx);
        float v = w[e] * m[e];
        __nv_bfloat16 h = __float2bfloat16(v);
        float lof = v - __bfloat162float(h);
        __nv_bfloat16 lo = __float2bfloat16(lof);
        sh[r][tx] = *(uint16_t*)&h;
        sl[r][tx] = *(uint16_t*)&lo;
    }
    __syncthreads();
    if (tx < 16) {
#pragma unroll
        for (int i = 0; i < 4; i++) {
            int r = ty + i * 8;                  // k-row of output
            size_t o = base + (size_t)(k0 + r) * NH + n0 + 2 * tx;  // elem idx
            uint32_t ph = (uint32_t)sh[2*tx][r] | ((uint32_t)sh[2*tx+1][r] << 16);
            uint32_t pl = (uint32_t)sl[2*tx][r] | ((uint32_t)sl[2*tx+1][r] << 16);
            *(uint32_t*)(g_whi + o * 2) = ph;
            *(uint32_t*)(g_wlo + o * 2) = pl;
        }
    }
}

// Prepass: split x into bf16 hi/lo (buffer 0), k-major [M][K].
__global__ void xsplit_kernel(const float* __restrict__ x) {
    size_t e = ((size_t)blockIdx.x * 256u + threadIdx.x) * 2u;
    float2 xv = *(const float2*)(x + e);
    __nv_bfloat16 h0 = __float2bfloat16(xv.x), h1 = __float2bfloat16(xv.y);
    float l0 = xv.x - __bfloat162float(h0), l1 = xv.y - __bfloat162float(h1);
    *(uint32_t*)(g_ahi[0] + e * 2) = pack2(h0, h1);
    *(uint32_t*)(g_alo[0] + e * 2) = pack2(__float2bfloat16(l0), __float2bfloat16(l1));
}

// ---------------------------------------------------------------------------
// Fused wmma GEMM + noise + relu + next-layer split.
// grid (32, 32): n0 = bx*128, m0 = by*128. 256 threads, 8 warps of 64x32.
// ---------------------------------------------------------------------------
__global__ void __launch_bounds__(256, 2)
gemm_tc_kernel(int layer, int abuf, int last,
               const float* __restrict__ z, const float* __restrict__ mu,
               const float* __restrict__ sig, float* __restrict__ out) {
    extern __shared__ __nv_bfloat16 smem[];
    const int tid = threadIdx.x;
    const int wid = tid >> 5;
    const int wm = wid >> 2;          // 0..1  (warp row: 64 rows)
    const int wn = wid & 3;           // 0..3  (warp col: 32 cols)
    const int n0 = blockIdx.x * BN;
    const int m0 = blockIdx.y * BM;
    const size_t NH2 = (size_t)NH * 2;

    const char* srcAh = g_ahi[abuf] + (size_t)m0 * NH2;
    const char* srcAl = g_alo[abuf] + (size_t)m0 * NH2;
    // Transposed W: [L][K][N]; tile base = layer plane + column n0.
    const char* srcWh = g_whi + ((size_t)layer * NH * NH + n0) * 2;
    const char* srcWl = g_wlo + ((size_t)layer * NH * NH + n0) * 2;

    // A: 128 rows x 64 B (4 chunks/row), 2 rows/thread per tile.
    const int rA0 = tid >> 2, rA1 = rA0 + 64, cA = tid & 3;
    // W-T: 32 rows x 256 B (16 chunks/row), 2 rows/thread per tile.
    const int rW0 = tid >> 4, rW1 = rW0 + 16, cW = tid & 15;

    auto load_stage = [&](int slot, int kt) {
        __nv_bfloat16* st = smem + slot * STAGE_E;
        const size_t kbA = (size_t)kt * 64;            // bytes along K (A)
        const size_t kbW = (size_t)kt * 32 * NH2;      // 32 k-rows (W-T)
        cp16(st + rA0 * LDSA + cA * 8,           srcAh + (size_t)rA0 * NH2 + kbA + cA * 16);
        cp16(st + rA1 * LDSA + cA * 8,           srcAh + (size_t)rA1 * NH2 + kbA + cA * 16);
        cp16(st + OFF_AL + rA0 * LDSA + cA * 8,  srcAl + (size_t)rA0 * NH2 + kbA + cA * 16);
        cp16(st + OFF_AL + rA1 * LDSA + cA * 8,  srcAl + (size_t)rA1 * NH2 + kbA + cA * 16);
        cp16(st + OFF_WH + rW0 * LDSWT + cW * 8, srcWh + kbW + (size_t)rW0 * NH2 + cW * 16);
        cp16(st + OFF_WH + rW1 * LDSWT + cW * 8, srcWh + kbW + (size_t)rW1 * NH2 + cW * 16);
        cp16(st + OFF_WL + rW0 * LDSWT + cW * 8, srcWl + kbW + (size_t)rW0 * NH2 + cW * 16);
        cp16(st + OFF_WL + rW1 * LDSWT + cW * 8, srcWl + kbW + (size_t)rW1 * NH2 + cW * 16);
    };

    wmma::fragment<wmma::accumulator, 16, 16, 16, float> acc[4][2];
#pragma unroll
    for (int i = 0; i < 4; i++)
#pragma unroll
        for (int j = 0; j < 2; j++) wmma::fill_fragment(acc[i][j], 0.0f);

    // Prologue: stages 0 and 1 (one group each).
    load_stage(0, 0); CP_COMMIT();
    load_stage(1, 1); CP_COMMIT();

    int slot = 0;
    for (int kt = 0; kt < NKT; kt++) {
        // Newest group is g_{kt+1}: wait_group 1 retires g_kt, barrier gives
        // cross-thread visibility AND all warps done compute kt-1, so buffer
        // (slot+2)%3 == buffer of kt-1 is free to overwrite after the sync.
        CP_WAIT1();
        __syncthreads();
        if (kt + 2 < NKT) load_stage((slot + 2) % STAGES, kt + 2);
        CP_COMMIT();   // unconditional: empty group keeps the count exact

        const __nv_bfloat16* st  = smem + slot * STAGE_E;
        const __nv_bfloat16* sAh = st;
        const __nv_bfloat16* sAl = st + OFF_AL;
        const __nv_bfloat16* sWh = st + OFF_WH;
        const __nv_bfloat16* sWl = st + OFF_WL;

#pragma unroll
        for (int ks = 0; ks < 2; ks++) {
            // Hold all A frags (32 regs), stream B frags one j at a time.
            wmma::fragment<wmma::matrix_a, 16, 16, 16, __nv_bfloat16, wmma::row_major> aH[4], aL[4];
#pragma unroll
            for (int i = 0; i < 4; i++) {
                const int ro = (wm * 64 + i * 16) * LDSA + ks * 16;
                wmma::load_matrix_sync(aH[i], sAh + ro, LDSA);
                wmma::load_matrix_sync(aL[i], sAl + ro, LDSA);
            }
#pragma unroll
            for (int j = 0; j < 2; j++) {
                // B row_major over [K][N]: k-offset rows, n-offset cols.
                wmma::fragment<wmma::matrix_b, 16, 16, 16, __nv_bfloat16, wmma::row_major> bH, bL;
                const int ro = (ks * 16) * LDSWT + wn * 32 + j * 16;
                wmma::load_matrix_sync(bH, sWh + ro, LDSWT);
                wmma::load_matrix_sync(bL, sWl + ro, LDSWT);
#pragma unroll
                for (int i = 0; i < 4; i++) {
                    wmma::mma_sync(acc[i][j], aH[i], bH, acc[i][j]);
                    wmma::mma_sync(acc[i][j], aH[i], bL, acc[i][j]);
                    wmma::mma_sync(acc[i][j], aL[i], bH, acc[i][j]);
                }
            }
        }
        slot = (slot + 1 == STAGES) ? 0 : slot + 1;
    }
    __syncthreads();   // all warps done with final stage before fb overwrite

    // ------------------------- epilogue ------------------------------------
    float* fb = (float*)smem;   // 128 x FB_LD fp32 = 67.6 KB < 113 KB
#pragma unroll
    for (int i = 0; i < 4; i++)
#pragma unroll
        for (int j = 0; j < 2; j++)
            wmma::store_matrix_sync(fb + (wm * 64 + i * 16) * FB_LD + wn * 32 + j * 16,
                                    acc[i][j], FB_LD, wmma::mem_row_major);
    __syncthreads();

    const float* zb = z + (size_t)m0 * NH + n0;
    float* ob = out + (size_t)m0 * (4 * NH) + n0;
    char* nxH = g_ahi[abuf ^ 1];
    char* nxL = g_alo[abuf ^ 1];

#pragma unroll
    for (int it = 0; it < 16; it++) {
        int idx4 = tid + it * 256;            // 0..4095 float4 slots
        int row  = idx4 >> 5;                 // 0..127
        int c4   = (idx4 & 31) << 2;          // 0..124

        float4 a  = *(float4*)&fb[row * FB_LD + c4];
        float4 zv = *(const float4*)(zb + (size_t)row * NH + c4);
        float4 mv = *(const float4*)(mu + n0 + c4);
        float4 sv = *(const float4*)(sig + n0 + c4);

        float v0 = fmaxf(a.x + __expf(fmaf(sv.x, zv.x, mv.x)), 0.0f);
        float v1 = fmaxf(a.y + __expf(fmaf(sv.y, zv.y, mv.y)), 0.0f);
        float v2 = fmaxf(a.z + __expf(fmaf(sv.z, zv.z, mv.z)), 0.0f);
        float v3 = fmaxf(a.w + __expf(fmaf(sv.w, zv.w, mv.w)), 0.0f);

        float4 o; o.x = v0; o.y = v1; o.z = v2; o.w = v3;
        *(float4*)(ob + (size_t)row * (4 * NH) + c4) = o;

        if (!last) {
            __nv_bfloat16 h0 = __float2bfloat16(v0), h1 = __float2bfloat16(v1);
            __nv_bfloat16 h2 = __float2bfloat16(v2), h3 = __float2bfloat16(v3);
            float l0 = v0 - __bfloat162float(h0), l1 = v1 - __bfloat162float(h1);
            float l2 = v2 - __bfloat162float(h2), l3 = v3 - __bfloat162float(h3);
            size_t off = ((size_t)(m0 + row) * NH + n0 + c4) * 2;  // bytes
            uint2 ph; ph.x = pack2(h0, h1); ph.y = pack2(h2, h3);
            uint2 pl; pl.x = pack2(__float2bfloat16(l0), __float2bfloat16(l1));
            pl.y = pack2(__float2bfloat16(l2), __float2bfloat16(l3));
            *(uint2*)(nxH + off) = ph;
            *(uint2*)(nxL + off) = pl;
        }
    }
}

// ---------------------------------------------------------------------------
// kernel_launch: prepasses + 4 chained fused GEMMs, graph-capturable.
// Inputs: x, weights, masks, mu, sigma, z. Output float32 [B, 4H].
// ---------------------------------------------------------------------------
extern "C" void kernel_launch(void* const* d_in, const int* in_sizes, int n_in,
                              void* d_out, int out_size) {
    const float* x   = (const float*)d_in[0];
    const float* w   = (const float*)d_in[1];
    const float* mk  = (const float*)d_in[2];
    const float* mu  = (const float*)d_in[3];
    const float* sg  = (const float*)d_in[4];
    const float* z   = (const float*)d_in[5];
    float*       out = (float*)d_out;

    cudaFuncSetAttribute(gemm_tc_kernel,
                         cudaFuncAttributeMaxDynamicSharedMemorySize, SMEM_BYTES);

    {   // W split + transpose to [L][K][N]
        dim3 g(NH / 32, NH / 32, NL);   // (128, 128, 4)
        wsplitT_kernel<<<g, 256>>>(w, mk);
    }
    {   // x split (k-major)
        unsigned blocks = (unsigned)(((size_t)NB * NH / 2) / 256);
        xsplit_kernel<<<blocks, 256>>>(x);
    }

    dim3 grid(NH / BN, NB / BM);  // (32, 32)
    for (int l = 0; l < NL; l++) {
        gemm_tc_kernel<<<grid, 256, SMEM_BYTES>>>(
            l, l & 1, (l == NL - 1) ? 1 : 0,
            z + (size_t)l * NB * NH,
            mu + (size_t)l * NH,
            sg + (size_t)l * NH,
            out + (size_t)l * NH);
    }
}